// round 10
// baseline (speedup 1.0000x reference)
#include <cuda_runtime.h>
#include <math.h>
#include <stdint.h>

#define LSEQ 512
#define DMOD 768
#define DIN  1536
#define DST  64
#define DCV  4
#define DRK  48
#define NXD  176   // DRK + 2*DST

// ---------------- scratch (device globals, no allocation) ----------------
__device__ float g_h[LSEQ * DMOD];
__device__ float g_xz[LSEQ * 2 * DIN];
__device__ float g_xconv[LSEQ * DIN];
__device__ float g_xdbl[LSEQ * NXD];
__device__ float g_dt[LSEQ * DIN];
__device__ float g_y[LSEQ * DIN];
__device__ float g_y2[LSEQ * DIN];
__device__ float g_xp_part[12 * LSEQ * NXD];   // x_proj split-K partials
__device__ float g_op_part[6 * LSEQ * DMOD];   // out_proj split-K partials

__device__ __forceinline__ uint32_t smem_u32(const void* p) {
    uint32_t a;
    asm("{ .reg .u64 t; cvta.to.shared.u64 t, %1; cvt.u32.u64 %0, t; }"
        : "=r"(a) : "l"(p));
    return a;
}
__device__ __forceinline__ void cp16(uint32_t dst, const float* src) {
    asm volatile("cp.async.cg.shared.global [%0], [%1], 16;"
                 :: "r"(dst), "l"(src) : "memory");
}
__device__ __forceinline__ void cp16z(uint32_t dst, const float* src, uint32_t sz) {
    asm volatile("cp.async.cg.shared.global [%0], [%1], 16, %2;"
                 :: "r"(dst), "l"(src), "r"(sz) : "memory");
}
#define CP_COMMIT() asm volatile("cp.async.commit_group;" ::: "memory")
#define CP_WAIT1()  asm volatile("cp.async.wait_group 1;" ::: "memory")
#define CP_WAIT0()  asm volatile("cp.async.wait_group 0;" ::: "memory")

// ======================= mma.sync tf32 GEMM (cp.async, 2-stage) ===========
// C[M,N] = A[M,K-slice] * W[N,K-slice]^T ; slice = blockIdx.z.
// K-tile 16; double-buffered smem, XOR-swizzled for conflict-free LDS.
// EPI 0: plain store; 2: softplus(acc + extra[n]).

template <int BM, int BN, int NWM, int NWN, int EPI>
__global__ __launch_bounds__(NWM * NWN * 32) void mma_gemm(
        const float* __restrict__ A, const float* __restrict__ W,
        float* __restrict__ C, const float* __restrict__ extra,
        int M, int N, int lda, int ldw, int ldc, int kslice) {
    constexpr int T  = NWM * NWN * 32;
    constexpr int WM = BM / NWM, WN = BN / NWN;
    constexpr int MT = WM / 16,  NT = WN / 8;
    constexpr int CA = BM * 4 / T, CB = BN * 4 / T;

    __shared__ float As[2 * BM * 16];
    __shared__ float Bs[2 * BN * 16];

    const int tid  = threadIdx.x;
    const int lane = tid & 31;
    const int wid  = tid >> 5;
    const int wm   = (wid / NWN) * WM;
    const int wn   = (wid % NWN) * WN;
    const int gid  = lane >> 2;
    const int ctib = lane & 3;
    const int m0 = blockIdx.y * BM;
    const int n0 = blockIdx.x * BN;
    const int kbeg = blockIdx.z * kslice;
    const int KTILES = kslice / 16;

    C += (size_t)blockIdx.z * M * ldc;

    const uint32_t sA = smem_u32(As);
    const uint32_t sB = smem_u32(Bs);

    float acc[MT][NT][4];
#pragma unroll
    for (int i = 0; i < MT; i++)
#pragma unroll
        for (int j = 0; j < NT; j++)
#pragma unroll
            for (int r = 0; r < 4; r++) acc[i][j][r] = 0.f;

    for (int kt = 0; kt <= KTILES; kt++) {
        if (kt < KTILES) {                   // stage tile kt -> buf kt&1
            int k0 = kbeg + kt * 16;
            uint32_t ab = sA + (kt & 1) * BM * 16 * 4;
            uint32_t bb = sB + (kt & 1) * BN * 16 * 4;
#pragma unroll
            for (int i = 0; i < CA; i++) {
                int idx = tid + i * T;
                int r = idx >> 2, g = idx & 3;
                uint32_t d = ab + (r * 16 + ((g ^ (r & 3)) << 2)) * 4;
                cp16(d, A + (size_t)(m0 + r) * lda + k0 + g * 4);
            }
#pragma unroll
            for (int i = 0; i < CB; i++) {
                int idx = tid + i * T;
                int r = idx >> 2, g = idx & 3;
                uint32_t d = bb + (r * 16 + ((g ^ (r & 3)) << 2)) * 4;
                int nr = n0 + r;
                int vr = (nr < N) ? nr : 0;
                cp16z(d, W + (size_t)vr * ldw + k0 + g * 4, (nr < N) ? 16u : 0u);
            }
            CP_COMMIT();
        }
        if (kt == 0) continue;

        if (kt < KTILES) CP_WAIT1(); else CP_WAIT0();
        __syncthreads();

        const float* Ab = As + ((kt - 1) & 1) * BM * 16;
        const float* Bb = Bs + ((kt - 1) & 1) * BN * 16;
#pragma unroll
        for (int ks = 0; ks < 2; ks++) {
            int kb = ks * 8;
            uint32_t af[MT][4], bf[NT][2];
#pragma unroll
            for (int mt = 0; mt < MT; mt++) {
                int r0 = wm + mt * 16 + gid;
                int r1 = r0 + 8;
                int c0 = kb + ctib, c1 = kb + ctib + 4;
                af[mt][0] = __float_as_uint(Ab[r0 * 16 + (((c0 >> 2) ^ (r0 & 3)) << 2) + ctib]);
                af[mt][1] = __float_as_uint(Ab[r1 * 16 + (((c0 >> 2) ^ (r1 & 3)) << 2) + ctib]);
                af[mt][2] = __float_as_uint(Ab[r0 * 16 + (((c1 >> 2) ^ (r0 & 3)) << 2) + ctib]);
                af[mt][3] = __float_as_uint(Ab[r1 * 16 + (((c1 >> 2) ^ (r1 & 3)) << 2) + ctib]);
            }
#pragma unroll
            for (int nt = 0; nt < NT; nt++) {
                int r = wn + nt * 8 + gid;
                int c0 = kb + ctib, c1 = kb + ctib + 4;
                bf[nt][0] = __float_as_uint(Bb[r * 16 + (((c0 >> 2) ^ (r & 3)) << 2) + ctib]);
                bf[nt][1] = __float_as_uint(Bb[r * 16 + (((c1 >> 2) ^ (r & 3)) << 2) + ctib]);
            }
#pragma unroll
            for (int mt = 0; mt < MT; mt++)
#pragma unroll
                for (int nt = 0; nt < NT; nt++) {
                    asm volatile(
                        "mma.sync.aligned.m16n8k8.row.col.f32.tf32.tf32.f32 "
                        "{%0,%1,%2,%3}, {%4,%5,%6,%7}, {%8,%9}, {%0,%1,%2,%3};"
                        : "+f"(acc[mt][nt][0]), "+f"(acc[mt][nt][1]),
                          "+f"(acc[mt][nt][2]), "+f"(acc[mt][nt][3])
                        : "r"(af[mt][0]), "r"(af[mt][1]),
                          "r"(af[mt][2]), "r"(af[mt][3]),
                          "r"(bf[nt][0]), "r"(bf[nt][1]));
                }
        }
        __syncthreads();
    }

    // ---- epilogue (float2 stores) ----
#pragma unroll
    for (int mt = 0; mt < MT; mt++) {
#pragma unroll
        for (int nt = 0; nt < NT; nt++) {
#pragma unroll
            for (int half = 0; half < 2; half++) {
                int gm = m0 + wm + mt * 16 + gid + half * 8;
                int gn = n0 + wn + nt * 8 + 2 * ctib;
                if (gn < N) {
                    float v0 = acc[mt][nt][half * 2];
                    float v1 = acc[mt][nt][half * 2 + 1];
                    if (EPI == 2) {
                        v0 += extra[gn];
                        v1 += extra[gn + 1];
                        v0 = (v0 > 20.f) ? v0 : log1pf(expf(v0));
                        v1 = (v1 > 20.f) ? v1 : log1pf(expf(v1));
                    }
                    *(float2*)&C[(size_t)gm * ldc + gn] = make_float2(v0, v1);
                }
            }
        }
    }
}

// ---------------- split-K reduce kernels ---------------------------------
__global__ void reduce_xp_kernel(const float4* __restrict__ part,
                                 float4* __restrict__ dst) {
    int i = blockIdx.x * blockDim.x + threadIdx.x;
    float4 s = part[i];
#pragma unroll
    for (int z = 1; z < 12; z++) {
        float4 v = part[i + z * (LSEQ * NXD / 4)];
        s.x += v.x; s.y += v.y; s.z += v.z; s.w += v.w;
    }
    dst[i] = s;
}
__global__ void reduce_out_kernel(const float4* __restrict__ part,
                                  const float4* __restrict__ res,
                                  float4* __restrict__ dst) {
    int i = blockIdx.x * blockDim.x + threadIdx.x;
    float4 s = res[i];
#pragma unroll
    for (int z = 0; z < 6; z++) {
        float4 v = part[i + z * (LSEQ * DMOD / 4)];
        s.x += v.x; s.y += v.y; s.z += v.z; s.w += v.w;
    }
    dst[i] = s;
}

// ---------------- layernorm: one block per row (768 cols) ----------------
__global__ void layernorm_kernel(const float* __restrict__ x,
                                 const float* __restrict__ w,
                                 const float* __restrict__ b,
                                 float* __restrict__ h) {
    int l = blockIdx.x;
    int t = threadIdx.x;
    const float* row = x + l * DMOD;
    float v[3];
    float sum = 0.f;
#pragma unroll
    for (int i = 0; i < 3; i++) { v[i] = row[t + 256 * i]; sum += v[i]; }

    __shared__ float red[256];
    red[t] = sum; __syncthreads();
    for (int s = 128; s > 0; s >>= 1) { if (t < s) red[t] += red[t + s]; __syncthreads(); }
    float mu = red[0] * (1.f / DMOD);
    __syncthreads();

    float sq = 0.f;
#pragma unroll
    for (int i = 0; i < 3; i++) { float d = v[i] - mu; sq += d * d; }
    red[t] = sq; __syncthreads();
    for (int s = 128; s > 0; s >>= 1) { if (t < s) red[t] += red[t + s]; __syncthreads(); }
    float rstd = rsqrtf(red[0] * (1.f / DMOD) + 1e-5f);

#pragma unroll
    for (int i = 0; i < 3; i++) {
        int c = t + 256 * i;
        h[l * DMOD + c] = (v[i] - mu) * rstd * w[c] + b[c];
    }
}

// ------------- causal depthwise conv (DC=4) + SiLU, float4 ---------------
__global__ void conv_silu_kernel(const float* __restrict__ xz,
                                 const float* __restrict__ cw,
                                 const float* __restrict__ cb,
                                 float* __restrict__ xc) {
    int idx = blockIdx.x * blockDim.x + threadIdx.x;   // LSEQ*DIN/4 threads
    if (idx >= LSEQ * (DIN / 4)) return;
    int l = idx / (DIN / 4);
    int d = (idx - l * (DIN / 4)) * 4;

    float4 acc = *(const float4*)&cb[d];
    float4 w0 = *(const float4*)&cw[(d + 0) * DCV];
    float4 w1 = *(const float4*)&cw[(d + 1) * DCV];
    float4 w2 = *(const float4*)&cw[(d + 2) * DCV];
    float4 w3 = *(const float4*)&cw[(d + 3) * DCV];
    const float* wj[4] = {&w0.x, &w1.x, &w2.x, &w3.x};

#pragma unroll
    for (int j = 0; j < DCV; j++) {
        int tl = l - (DCV - 1) + j;
        if (tl >= 0) {
            float4 v = *(const float4*)&xz[(size_t)tl * (2 * DIN) + d];
            acc.x += v.x * wj[0][j];
            acc.y += v.y * wj[1][j];
            acc.z += v.z * wj[2][j];
            acc.w += v.w * wj[3][j];
        }
    }
    float4 o;
    o.x = acc.x / (1.f + __expf(-acc.x));
    o.y = acc.y / (1.f + __expf(-acc.y));
    o.z = acc.z / (1.f + __expf(-acc.z));
    o.w = acc.w / (1.f + __expf(-acc.w));
    *(float4*)&xc[(size_t)l * DIN + d] = o;
}

// ---------------- selective scan: smem-staged, 1 warp/channel (R4) -------
__global__ __launch_bounds__(256) void scan_kernel(
        const float* __restrict__ xdbl, const float* __restrict__ dt,
        const float* __restrict__ xc, const float* __restrict__ A_log,
        float* __restrict__ y) {
    __shared__ float sBC[16][128];
    __shared__ float sdt[16][8];
    __shared__ float sxc[16][8];

    int tid  = threadIdx.x;
    int warp = tid >> 5;
    int lane = tid & 31;
    int d0 = blockIdx.x * 8;
    int d  = d0 + warp;

    float a0 = -__expf(A_log[d * DST + lane]);
    float a1 = -__expf(A_log[d * DST + 32 + lane]);
    float s0 = 0.f, s1 = 0.f;

    for (int lc = 0; lc < LSEQ; lc += 16) {
        __syncthreads();
#pragma unroll
        for (int k = 0; k < 2; k++) {
            int idx = tid + k * 256;
            int row = idx >> 5, c4 = (idx & 31) * 4;
            *(float4*)&sBC[row][c4] =
                *(const float4*)&xdbl[(size_t)(lc + row) * NXD + DRK + c4];
        }
        if (tid < 128) {
            int row = tid >> 3, dd = tid & 7;
            sdt[row][dd] = dt[(size_t)(lc + row) * DIN + d0 + dd];
        } else {
            int t2 = tid - 128;
            int row = t2 >> 3, dd = t2 & 7;
            sxc[row][dd] = xc[(size_t)(lc + row) * DIN + d0 + dd];
        }
        __syncthreads();

#pragma unroll 4
        for (int i = 0; i < 16; i++) {
            float dtv = sdt[i][warp];
            float u   = sxc[i][warp];
            float B0 = sBC[i][lane],      B1 = sBC[i][32 + lane];
            float C0 = sBC[i][64 + lane], C1 = sBC[i][96 + lane];
            float dbu = dtv * u;
            s0 = __expf(dtv * a0) * s0 + dbu * B0;
            s1 = __expf(dtv * a1) * s1 + dbu * B1;
            float p = s0 * C0 + s1 * C1;
#pragma unroll
            for (int off = 16; off > 0; off >>= 1)
                p += __shfl_xor_sync(0xffffffffu, p, off);
            if (lane == 0) y[(size_t)(lc + i) * DIN + d] = p;
        }
    }
}

// ------------- y2 = (y + xc*D) * silu(z), float4 --------------------------
__global__ void final_elem_kernel(const float* __restrict__ y,
                                  const float* __restrict__ xc,
                                  const float* __restrict__ xz,
                                  const float* __restrict__ Dv,
                                  float* __restrict__ y2) {
    int idx = blockIdx.x * blockDim.x + threadIdx.x;   // LSEQ*DIN/4 threads
    if (idx >= LSEQ * (DIN / 4)) return;
    int l = idx / (DIN / 4);
    int d = (idx - l * (DIN / 4)) * 4;

    float4 zv = *(const float4*)&xz[(size_t)l * (2 * DIN) + DIN + d];
    float4 yv = *(const float4*)&y[(size_t)l * DIN + d];
    float4 uv = *(const float4*)&xc[(size_t)l * DIN + d];
    float4 Dv4 = *(const float4*)&Dv[d];
    float4 o;
    o.x = (yv.x + uv.x * Dv4.x) * (zv.x / (1.f + __expf(-zv.x)));
    o.y = (yv.y + uv.y * Dv4.y) * (zv.y / (1.f + __expf(-zv.y)));
    o.z = (yv.z + uv.z * Dv4.z) * (zv.z / (1.f + __expf(-zv.z)));
    o.w = (yv.w + uv.w * Dv4.w) * (zv.w / (1.f + __expf(-zv.w)));
    *(float4*)&y2[(size_t)l * DIN + d] = o;
}

// ---------------- launch --------------------------------------------------
extern "C" void kernel_launch(void* const* d_in, const int* in_sizes, int n_in,
                              void* d_out, int out_size) {
    const float* x          = (const float*)d_in[0];
    const float* ln_w       = (const float*)d_in[1];
    const float* ln_b       = (const float*)d_in[2];
    const float* in_proj_w  = (const float*)d_in[3];
    const float* conv_w     = (const float*)d_in[4];
    const float* conv_b     = (const float*)d_in[5];
    const float* x_proj_w   = (const float*)d_in[6];
    const float* dt_proj_w  = (const float*)d_in[7];
    const float* dt_proj_b  = (const float*)d_in[8];
    const float* A_log      = (const float*)d_in[9];
    const float* Dvec       = (const float*)d_in[10];
    const float* out_proj_w = (const float*)d_in[11];
    float* out = (float*)d_out;

    float *h, *xz, *xc, *xdbl, *dt, *y, *y2, *xpp, *opp;
    cudaGetSymbolAddress((void**)&h,    g_h);
    cudaGetSymbolAddress((void**)&xz,   g_xz);
    cudaGetSymbolAddress((void**)&xc,   g_xconv);
    cudaGetSymbolAddress((void**)&xdbl, g_xdbl);
    cudaGetSymbolAddress((void**)&dt,   g_dt);
    cudaGetSymbolAddress((void**)&y,    g_y);
    cudaGetSymbolAddress((void**)&y2,   g_y2);
    cudaGetSymbolAddress((void**)&xpp,  g_xp_part);
    cudaGetSymbolAddress((void**)&opp,  g_op_part);

    // 1) layernorm
    layernorm_kernel<<<LSEQ, 256>>>(x, ln_w, ln_b, h);

    // 2) in_proj: [512,768] x [3072,768]^T -> [512,3072]   (96 CTAs, R4 config)
    mma_gemm<128, 128, 2, 4, 0><<<dim3(24, 4, 1), 256>>>(
        h, in_proj_w, xz, nullptr, LSEQ, 2 * DIN, DMOD, DMOD, 2 * DIN, DMOD);

    // 3) causal depthwise conv + silu -> xc [512,1536]  (float4)
    conv_silu_kernel<<<(LSEQ * DIN / 4) / 256, 256>>>(xz, conv_w, conv_b, xc);

    // 4) x_proj split-K(12): [512,1536] x [176,1536]^T -> partials (288 CTAs)
    mma_gemm<64, 64, 2, 2, 0><<<dim3(3, 8, 12), 128>>>(
        xc, x_proj_w, xpp, nullptr, LSEQ, NXD, DIN, DIN, NXD, 128);
    reduce_xp_kernel<<<(LSEQ * NXD / 4) / 256, 256>>>(
        (const float4*)xpp, (float4*)xdbl);

    // 5) dt_proj + softplus: [512,48](lda=176) x [1536,48]^T -> [512,1536] (192 CTAs)
    mma_gemm<64, 64, 2, 2, 2><<<dim3(24, 8, 1), 128>>>(
        xdbl, dt_proj_w, dt, dt_proj_b, LSEQ, DIN, NXD, DRK, DIN, DRK);

    // 6) selective scan -> y [512,1536]  (R4 form)
    scan_kernel<<<DIN / 8, 256>>>(xdbl, dt, xc, A_log, y);

    // 7) y2 = (y + xc*D) * silu(z)  (float4)
    final_elem_kernel<<<(LSEQ * DIN / 4) / 256, 256>>>(y, xc, xz, Dvec, y2);

    // 8) out_proj split-K(6): [512,1536] x [768,1536]^T -> partials (144 CTAs, R4 config)
    mma_gemm<128, 128, 2, 4, 0><<<dim3(6, 4, 6), 256>>>(
        y2, out_proj_w, opp, nullptr, LSEQ, DMOD, DIN, DIN, DMOD, 256);
    reduce_out_kernel<<<(LSEQ * DMOD / 4) / 256, 256>>>(
        (const float4*)opp, (const float4*)x, (float4*)out);
}

// round 11
// speedup vs baseline: 1.0018x; 1.0018x over previous
#include <cuda_runtime.h>
#include <math.h>
#include <stdint.h>

#define LSEQ 512
#define DMOD 768
#define DIN  1536
#define DST  64
#define DCV  4
#define DRK  48
#define NXD  176   // DRK + 2*DST

// ---------------- scratch (device globals, no allocation) ----------------
__device__ float g_h[LSEQ * DMOD];
__device__ float g_xz[LSEQ * 2 * DIN];
__device__ float g_xconv[LSEQ * DIN];
__device__ float g_xdbl[LSEQ * NXD];
__device__ float g_dt[LSEQ * DIN];
__device__ float g_y[LSEQ * DIN];
__device__ float g_y2[LSEQ * DIN];
__device__ float g_xp_part[12 * LSEQ * NXD];   // x_proj split-K partials
__device__ float g_op_part[6 * LSEQ * DMOD];   // out_proj split-K partials

__device__ __forceinline__ uint32_t smem_u32(const void* p) {
    uint32_t a;
    asm("{ .reg .u64 t; cvta.to.shared.u64 t, %1; cvt.u32.u64 %0, t; }"
        : "=r"(a) : "l"(p));
    return a;
}
__device__ __forceinline__ void cp16(uint32_t dst, const float* src) {
    asm volatile("cp.async.cg.shared.global [%0], [%1], 16;"
                 :: "r"(dst), "l"(src) : "memory");
}
__device__ __forceinline__ void cp16z(uint32_t dst, const float* src, uint32_t sz) {
    asm volatile("cp.async.cg.shared.global [%0], [%1], 16, %2;"
                 :: "r"(dst), "l"(src), "r"(sz) : "memory");
}
#define CP_COMMIT() asm volatile("cp.async.commit_group;" ::: "memory")
#define CP_WAIT1()  asm volatile("cp.async.wait_group 1;" ::: "memory")
#define CP_WAIT0()  asm volatile("cp.async.wait_group 0;" ::: "memory")

// ======================= mma.sync tf32 GEMM (cp.async, 2-stage) ===========
// C[M,N] = A[M,K-slice] * W[N,K-slice]^T ; slice = blockIdx.z.
// K-tile 16; double-buffered smem, XOR-swizzled for conflict-free LDS.
// EPI 0: plain store; 2: softplus(acc + extra[n]).

template <int BM, int BN, int NWM, int NWN, int EPI>
__global__ __launch_bounds__(NWM * NWN * 32) void mma_gemm(
        const float* __restrict__ A, const float* __restrict__ W,
        float* __restrict__ C, const float* __restrict__ extra,
        int M, int N, int lda, int ldw, int ldc, int kslice) {
    constexpr int T  = NWM * NWN * 32;
    constexpr int WM = BM / NWM, WN = BN / NWN;
    constexpr int MT = WM / 16,  NT = WN / 8;
    constexpr int CA = BM * 4 / T, CB = BN * 4 / T;

    __shared__ float As[2 * BM * 16];
    __shared__ float Bs[2 * BN * 16];

    const int tid  = threadIdx.x;
    const int lane = tid & 31;
    const int wid  = tid >> 5;
    const int wm   = (wid / NWN) * WM;
    const int wn   = (wid % NWN) * WN;
    const int gid  = lane >> 2;
    const int ctib = lane & 3;
    const int m0 = blockIdx.y * BM;
    const int n0 = blockIdx.x * BN;
    const int kbeg = blockIdx.z * kslice;
    const int KTILES = kslice / 16;

    C += (size_t)blockIdx.z * M * ldc;

    const uint32_t sA = smem_u32(As);
    const uint32_t sB = smem_u32(Bs);

    float acc[MT][NT][4];
#pragma unroll
    for (int i = 0; i < MT; i++)
#pragma unroll
        for (int j = 0; j < NT; j++)
#pragma unroll
            for (int r = 0; r < 4; r++) acc[i][j][r] = 0.f;

    for (int kt = 0; kt <= KTILES; kt++) {
        if (kt < KTILES) {                   // stage tile kt -> buf kt&1
            int k0 = kbeg + kt * 16;
            uint32_t ab = sA + (kt & 1) * BM * 16 * 4;
            uint32_t bb = sB + (kt & 1) * BN * 16 * 4;
#pragma unroll
            for (int i = 0; i < CA; i++) {
                int idx = tid + i * T;
                int r = idx >> 2, g = idx & 3;
                uint32_t d = ab + (r * 16 + ((g ^ (r & 3)) << 2)) * 4;
                cp16(d, A + (size_t)(m0 + r) * lda + k0 + g * 4);
            }
#pragma unroll
            for (int i = 0; i < CB; i++) {
                int idx = tid + i * T;
                int r = idx >> 2, g = idx & 3;
                uint32_t d = bb + (r * 16 + ((g ^ (r & 3)) << 2)) * 4;
                int nr = n0 + r;
                int vr = (nr < N) ? nr : 0;
                cp16z(d, W + (size_t)vr * ldw + k0 + g * 4, (nr < N) ? 16u : 0u);
            }
            CP_COMMIT();
        }
        if (kt == 0) continue;

        if (kt < KTILES) CP_WAIT1(); else CP_WAIT0();
        __syncthreads();

        const float* Ab = As + ((kt - 1) & 1) * BM * 16;
        const float* Bb = Bs + ((kt - 1) & 1) * BN * 16;
#pragma unroll
        for (int ks = 0; ks < 2; ks++) {
            int kb = ks * 8;
            uint32_t af[MT][4], bf[NT][2];
#pragma unroll
            for (int mt = 0; mt < MT; mt++) {
                int r0 = wm + mt * 16 + gid;
                int r1 = r0 + 8;
                int c0 = kb + ctib, c1 = kb + ctib + 4;
                af[mt][0] = __float_as_uint(Ab[r0 * 16 + (((c0 >> 2) ^ (r0 & 3)) << 2) + ctib]);
                af[mt][1] = __float_as_uint(Ab[r1 * 16 + (((c0 >> 2) ^ (r1 & 3)) << 2) + ctib]);
                af[mt][2] = __float_as_uint(Ab[r0 * 16 + (((c1 >> 2) ^ (r0 & 3)) << 2) + ctib]);
                af[mt][3] = __float_as_uint(Ab[r1 * 16 + (((c1 >> 2) ^ (r1 & 3)) << 2) + ctib]);
            }
#pragma unroll
            for (int nt = 0; nt < NT; nt++) {
                int r = wn + nt * 8 + gid;
                int c0 = kb + ctib, c1 = kb + ctib + 4;
                bf[nt][0] = __float_as_uint(Bb[r * 16 + (((c0 >> 2) ^ (r & 3)) << 2) + ctib]);
                bf[nt][1] = __float_as_uint(Bb[r * 16 + (((c1 >> 2) ^ (r & 3)) << 2) + ctib]);
            }
#pragma unroll
            for (int mt = 0; mt < MT; mt++)
#pragma unroll
                for (int nt = 0; nt < NT; nt++) {
                    asm volatile(
                        "mma.sync.aligned.m16n8k8.row.col.f32.tf32.tf32.f32 "
                        "{%0,%1,%2,%3}, {%4,%5,%6,%7}, {%8,%9}, {%0,%1,%2,%3};"
                        : "+f"(acc[mt][nt][0]), "+f"(acc[mt][nt][1]),
                          "+f"(acc[mt][nt][2]), "+f"(acc[mt][nt][3])
                        : "r"(af[mt][0]), "r"(af[mt][1]),
                          "r"(af[mt][2]), "r"(af[mt][3]),
                          "r"(bf[nt][0]), "r"(bf[nt][1]));
                }
        }
        __syncthreads();
    }

    // ---- epilogue (float2 stores) ----
#pragma unroll
    for (int mt = 0; mt < MT; mt++) {
#pragma unroll
        for (int nt = 0; nt < NT; nt++) {
#pragma unroll
            for (int half = 0; half < 2; half++) {
                int gm = m0 + wm + mt * 16 + gid + half * 8;
                int gn = n0 + wn + nt * 8 + 2 * ctib;
                if (gn < N) {
                    float v0 = acc[mt][nt][half * 2];
                    float v1 = acc[mt][nt][half * 2 + 1];
                    if (EPI == 2) {
                        v0 += extra[gn];
                        v1 += extra[gn + 1];
                        v0 = (v0 > 20.f) ? v0 : log1pf(expf(v0));
                        v1 = (v1 > 20.f) ? v1 : log1pf(expf(v1));
                    }
                    *(float2*)&C[(size_t)gm * ldc + gn] = make_float2(v0, v1);
                }
            }
        }
    }
}

// ---------------- split-K reduce kernels ---------------------------------
__global__ void reduce_xp_kernel(const float4* __restrict__ part,
                                 float4* __restrict__ dst) {
    int i = blockIdx.x * blockDim.x + threadIdx.x;
    float4 s = part[i];
#pragma unroll
    for (int z = 1; z < 12; z++) {
        float4 v = part[i + z * (LSEQ * NXD / 4)];
        s.x += v.x; s.y += v.y; s.z += v.z; s.w += v.w;
    }
    dst[i] = s;
}
__global__ void reduce_out_kernel(const float4* __restrict__ part,
                                  const float4* __restrict__ res,
                                  float4* __restrict__ dst) {
    int i = blockIdx.x * blockDim.x + threadIdx.x;
    float4 s = res[i];
#pragma unroll
    for (int z = 0; z < 6; z++) {
        float4 v = part[i + z * (LSEQ * DMOD / 4)];
        s.x += v.x; s.y += v.y; s.z += v.z; s.w += v.w;
    }
    dst[i] = s;
}

// ---------------- layernorm: one block per row (768 cols) ----------------
__global__ void layernorm_kernel(const float* __restrict__ x,
                                 const float* __restrict__ w,
                                 const float* __restrict__ b,
                                 float* __restrict__ h) {
    int l = blockIdx.x;
    int t = threadIdx.x;
    const float* row = x + l * DMOD;
    float v[3];
    float sum = 0.f;
#pragma unroll
    for (int i = 0; i < 3; i++) { v[i] = row[t + 256 * i]; sum += v[i]; }

    __shared__ float red[256];
    red[t] = sum; __syncthreads();
    for (int s = 128; s > 0; s >>= 1) { if (t < s) red[t] += red[t + s]; __syncthreads(); }
    float mu = red[0] * (1.f / DMOD);
    __syncthreads();

    float sq = 0.f;
#pragma unroll
    for (int i = 0; i < 3; i++) { float d = v[i] - mu; sq += d * d; }
    red[t] = sq; __syncthreads();
    for (int s = 128; s > 0; s >>= 1) { if (t < s) red[t] += red[t + s]; __syncthreads(); }
    float rstd = rsqrtf(red[0] * (1.f / DMOD) + 1e-5f);

#pragma unroll
    for (int i = 0; i < 3; i++) {
        int c = t + 256 * i;
        h[l * DMOD + c] = (v[i] - mu) * rstd * w[c] + b[c];
    }
}

// ------------- causal depthwise conv (DC=4) + SiLU, float4 ---------------
__global__ void conv_silu_kernel(const float* __restrict__ xz,
                                 const float* __restrict__ cw,
                                 const float* __restrict__ cb,
                                 float* __restrict__ xc) {
    int idx = blockIdx.x * blockDim.x + threadIdx.x;   // LSEQ*DIN/4 threads
    if (idx >= LSEQ * (DIN / 4)) return;
    int l = idx / (DIN / 4);
    int d = (idx - l * (DIN / 4)) * 4;

    float4 acc = *(const float4*)&cb[d];
    float4 w0 = *(const float4*)&cw[(d + 0) * DCV];
    float4 w1 = *(const float4*)&cw[(d + 1) * DCV];
    float4 w2 = *(const float4*)&cw[(d + 2) * DCV];
    float4 w3 = *(const float4*)&cw[(d + 3) * DCV];
    const float* wj[4] = {&w0.x, &w1.x, &w2.x, &w3.x};

#pragma unroll
    for (int j = 0; j < DCV; j++) {
        int tl = l - (DCV - 1) + j;
        if (tl >= 0) {
            float4 v = *(const float4*)&xz[(size_t)tl * (2 * DIN) + d];
            acc.x += v.x * wj[0][j];
            acc.y += v.y * wj[1][j];
            acc.z += v.z * wj[2][j];
            acc.w += v.w * wj[3][j];
        }
    }
    float4 o;
    o.x = acc.x / (1.f + __expf(-acc.x));
    o.y = acc.y / (1.f + __expf(-acc.y));
    o.z = acc.z / (1.f + __expf(-acc.z));
    o.w = acc.w / (1.f + __expf(-acc.w));
    *(float4*)&xc[(size_t)l * DIN + d] = o;
}

// ---------------- selective scan: smem-staged, 1 warp/channel (R4) -------
__global__ __launch_bounds__(256) void scan_kernel(
        const float* __restrict__ xdbl, const float* __restrict__ dt,
        const float* __restrict__ xc, const float* __restrict__ A_log,
        float* __restrict__ y) {
    __shared__ float sBC[16][128];
    __shared__ float sdt[16][8];
    __shared__ float sxc[16][8];

    int tid  = threadIdx.x;
    int warp = tid >> 5;
    int lane = tid & 31;
    int d0 = blockIdx.x * 8;
    int d  = d0 + warp;

    float a0 = -__expf(A_log[d * DST + lane]);
    float a1 = -__expf(A_log[d * DST + 32 + lane]);
    float s0 = 0.f, s1 = 0.f;

    for (int lc = 0; lc < LSEQ; lc += 16) {
        __syncthreads();
#pragma unroll
        for (int k = 0; k < 2; k++) {
            int idx = tid + k * 256;
            int row = idx >> 5, c4 = (idx & 31) * 4;
            *(float4*)&sBC[row][c4] =
                *(const float4*)&xdbl[(size_t)(lc + row) * NXD + DRK + c4];
        }
        if (tid < 128) {
            int row = tid >> 3, dd = tid & 7;
            sdt[row][dd] = dt[(size_t)(lc + row) * DIN + d0 + dd];
        } else {
            int t2 = tid - 128;
            int row = t2 >> 3, dd = t2 & 7;
            sxc[row][dd] = xc[(size_t)(lc + row) * DIN + d0 + dd];
        }
        __syncthreads();

#pragma unroll 4
        for (int i = 0; i < 16; i++) {
            float dtv = sdt[i][warp];
            float u   = sxc[i][warp];
            float B0 = sBC[i][lane],      B1 = sBC[i][32 + lane];
            float C0 = sBC[i][64 + lane], C1 = sBC[i][96 + lane];
            float dbu = dtv * u;
            s0 = __expf(dtv * a0) * s0 + dbu * B0;
            s1 = __expf(dtv * a1) * s1 + dbu * B1;
            float p = s0 * C0 + s1 * C1;
#pragma unroll
            for (int off = 16; off > 0; off >>= 1)
                p += __shfl_xor_sync(0xffffffffu, p, off);
            if (lane == 0) y[(size_t)(lc + i) * DIN + d] = p;
        }
    }
}

// ------------- y2 = (y + xc*D) * silu(z), float4 --------------------------
__global__ void final_elem_kernel(const float* __restrict__ y,
                                  const float* __restrict__ xc,
                                  const float* __restrict__ xz,
                                  const float* __restrict__ Dv,
                                  float* __restrict__ y2) {
    int idx = blockIdx.x * blockDim.x + threadIdx.x;   // LSEQ*DIN/4 threads
    if (idx >= LSEQ * (DIN / 4)) return;
    int l = idx / (DIN / 4);
    int d = (idx - l * (DIN / 4)) * 4;

    float4 zv = *(const float4*)&xz[(size_t)l * (2 * DIN) + DIN + d];
    float4 yv = *(const float4*)&y[(size_t)l * DIN + d];
    float4 uv = *(const float4*)&xc[(size_t)l * DIN + d];
    float4 Dv4 = *(const float4*)&Dv[d];
    float4 o;
    o.x = (yv.x + uv.x * Dv4.x) * (zv.x / (1.f + __expf(-zv.x)));
    o.y = (yv.y + uv.y * Dv4.y) * (zv.y / (1.f + __expf(-zv.y)));
    o.z = (yv.z + uv.z * Dv4.z) * (zv.z / (1.f + __expf(-zv.z)));
    o.w = (yv.w + uv.w * Dv4.w) * (zv.w / (1.f + __expf(-zv.w)));
    *(float4*)&y2[(size_t)l * DIN + d] = o;
}

// ---------------- launch --------------------------------------------------
extern "C" void kernel_launch(void* const* d_in, const int* in_sizes, int n_in,
                              void* d_out, int out_size) {
    const float* x          = (const float*)d_in[0];
    const float* ln_w       = (const float*)d_in[1];
    const float* ln_b       = (const float*)d_in[2];
    const float* in_proj_w  = (const float*)d_in[3];
    const float* conv_w     = (const float*)d_in[4];
    const float* conv_b     = (const float*)d_in[5];
    const float* x_proj_w   = (const float*)d_in[6];
    const float* dt_proj_w  = (const float*)d_in[7];
    const float* dt_proj_b  = (const float*)d_in[8];
    const float* A_log      = (const float*)d_in[9];
    const float* Dvec       = (const float*)d_in[10];
    const float* out_proj_w = (const float*)d_in[11];
    float* out = (float*)d_out;

    float *h, *xz, *xc, *xdbl, *dt, *y, *y2, *xpp, *opp;
    cudaGetSymbolAddress((void**)&h,    g_h);
    cudaGetSymbolAddress((void**)&xz,   g_xz);
    cudaGetSymbolAddress((void**)&xc,   g_xconv);
    cudaGetSymbolAddress((void**)&xdbl, g_xdbl);
    cudaGetSymbolAddress((void**)&dt,   g_dt);
    cudaGetSymbolAddress((void**)&y,    g_y);
    cudaGetSymbolAddress((void**)&y2,   g_y2);
    cudaGetSymbolAddress((void**)&xpp,  g_xp_part);
    cudaGetSymbolAddress((void**)&opp,  g_op_part);

    // 1) layernorm
    layernorm_kernel<<<LSEQ, 256>>>(x, ln_w, ln_b, h);

    // 2) in_proj: [512,768] x [3072,768]^T -> [512,3072]   (96 CTAs, R4 config)
    mma_gemm<128, 128, 2, 4, 0><<<dim3(24, 4, 1), 256>>>(
        h, in_proj_w, xz, nullptr, LSEQ, 2 * DIN, DMOD, DMOD, 2 * DIN, DMOD);

    // 3) causal depthwise conv + silu -> xc [512,1536]  (float4)
    conv_silu_kernel<<<(LSEQ * DIN / 4) / 256, 256>>>(xz, conv_w, conv_b, xc);

    // 4) x_proj split-K(12): [512,1536] x [176,1536]^T -> partials (288 CTAs)
    mma_gemm<64, 64, 2, 2, 0><<<dim3(3, 8, 12), 128>>>(
        xc, x_proj_w, xpp, nullptr, LSEQ, NXD, DIN, DIN, NXD, 128);
    reduce_xp_kernel<<<(LSEQ * NXD / 4) / 256, 256>>>(
        (const float4*)xpp, (float4*)xdbl);

    // 5) dt_proj + softplus: [512,48](lda=176) x [1536,48]^T -> [512,1536] (192 CTAs)
    mma_gemm<64, 64, 2, 2, 2><<<dim3(24, 8, 1), 128>>>(
        xdbl, dt_proj_w, dt, dt_proj_b, LSEQ, DIN, NXD, DRK, DIN, DRK);

    // 6) selective scan -> y [512,1536]  (R4 form)
    scan_kernel<<<DIN / 8, 256>>>(xdbl, dt, xc, A_log, y);

    // 7) y2 = (y + xc*D) * silu(z)  (float4)
    final_elem_kernel<<<(LSEQ * DIN / 4) / 256, 256>>>(y, xc, xz, Dvec, y2);

    // 8) out_proj split-K(6): [512,1536] x [768,1536]^T -> partials (144 CTAs, R4 config)
    mma_gemm<128, 128, 2, 4, 0><<<dim3(6, 4, 6), 256>>>(
        y2, out_proj_w, opp, nullptr, LSEQ, DMOD, DIN, DIN, DMOD, 256);
    reduce_out_kernel<<<(LSEQ * DMOD / 4) / 256, 256>>>(
        (const float4*)opp, (const float4*)x, (float4*)out);
}

// round 12
// speedup vs baseline: 1.0044x; 1.0026x over previous
#include <cuda_runtime.h>
#include <math.h>
#include <stdint.h>

#define LSEQ 512
#define DMOD 768
#define DIN  1536
#define DST  64
#define DCV  4
#define DRK  48
#define NXD  176   // DRK + 2*DST

// ---------------- scratch (device globals, no allocation) ----------------
__device__ float g_h[LSEQ * DMOD];
__device__ float g_xz[LSEQ * 2 * DIN];
__device__ float g_xconv[LSEQ * DIN];
__device__ float g_xdbl[LSEQ * NXD];
__device__ float g_dt[LSEQ * DIN];
__device__ float g_y[LSEQ * DIN];
__device__ float g_y2[LSEQ * DIN];
__device__ float g_xp_part[12 * LSEQ * NXD];   // x_proj split-K partials
__device__ float g_op_part[6 * LSEQ * DMOD];   // out_proj split-K partials

__device__ __forceinline__ uint32_t smem_u32(const void* p) {
    uint32_t a;
    asm("{ .reg .u64 t; cvta.to.shared.u64 t, %1; cvt.u32.u64 %0, t; }"
        : "=r"(a) : "l"(p));
    return a;
}
__device__ __forceinline__ void cp16(uint32_t dst, const float* src) {
    asm volatile("cp.async.cg.shared.global [%0], [%1], 16;"
                 :: "r"(dst), "l"(src) : "memory");
}
__device__ __forceinline__ void cp16z(uint32_t dst, const float* src, uint32_t sz) {
    asm volatile("cp.async.cg.shared.global [%0], [%1], 16, %2;"
                 :: "r"(dst), "l"(src), "r"(sz) : "memory");
}
#define CP_COMMIT() asm volatile("cp.async.commit_group;" ::: "memory")
#define CP_WAIT1()  asm volatile("cp.async.wait_group 1;" ::: "memory")
#define CP_WAIT0()  asm volatile("cp.async.wait_group 0;" ::: "memory")

// ======================= mma.sync tf32 GEMM (cp.async, 2-stage) ===========
// C[M,N] = A[M,K-slice] * W[N,K-slice]^T ; slice = blockIdx.z.
// K-tile 16; double-buffered smem, XOR-swizzled for conflict-free LDS.
// EPI 0: plain store; 2: softplus(acc + extra[n]).

template <int BM, int BN, int NWM, int NWN, int EPI>
__global__ __launch_bounds__(NWM * NWN * 32) void mma_gemm(
        const float* __restrict__ A, const float* __restrict__ W,
        float* __restrict__ C, const float* __restrict__ extra,
        int M, int N, int lda, int ldw, int ldc, int kslice) {
    constexpr int T  = NWM * NWN * 32;
    constexpr int WM = BM / NWM, WN = BN / NWN;
    constexpr int MT = WM / 16,  NT = WN / 8;
    constexpr int CA = BM * 4 / T, CB = BN * 4 / T;

    __shared__ float As[2 * BM * 16];
    __shared__ float Bs[2 * BN * 16];

    const int tid  = threadIdx.x;
    const int lane = tid & 31;
    const int wid  = tid >> 5;
    const int wm   = (wid / NWN) * WM;
    const int wn   = (wid % NWN) * WN;
    const int gid  = lane >> 2;
    const int ctib = lane & 3;
    const int m0 = blockIdx.y * BM;
    const int n0 = blockIdx.x * BN;
    const int kbeg = blockIdx.z * kslice;
    const int KTILES = kslice / 16;

    C += (size_t)blockIdx.z * M * ldc;

    const uint32_t sA = smem_u32(As);
    const uint32_t sB = smem_u32(Bs);

    float acc[MT][NT][4];
#pragma unroll
    for (int i = 0; i < MT; i++)
#pragma unroll
        for (int j = 0; j < NT; j++)
#pragma unroll
            for (int r = 0; r < 4; r++) acc[i][j][r] = 0.f;

    for (int kt = 0; kt <= KTILES; kt++) {
        if (kt < KTILES) {                   // stage tile kt -> buf kt&1
            int k0 = kbeg + kt * 16;
            uint32_t ab = sA + (kt & 1) * BM * 16 * 4;
            uint32_t bb = sB + (kt & 1) * BN * 16 * 4;
#pragma unroll
            for (int i = 0; i < CA; i++) {
                int idx = tid + i * T;
                int r = idx >> 2, g = idx & 3;
                uint32_t d = ab + (r * 16 + ((g ^ (r & 3)) << 2)) * 4;
                cp16(d, A + (size_t)(m0 + r) * lda + k0 + g * 4);
            }
#pragma unroll
            for (int i = 0; i < CB; i++) {
                int idx = tid + i * T;
                int r = idx >> 2, g = idx & 3;
                uint32_t d = bb + (r * 16 + ((g ^ (r & 3)) << 2)) * 4;
                int nr = n0 + r;
                int vr = (nr < N) ? nr : 0;
                cp16z(d, W + (size_t)vr * ldw + k0 + g * 4, (nr < N) ? 16u : 0u);
            }
            CP_COMMIT();
        }
        if (kt == 0) continue;

        if (kt < KTILES) CP_WAIT1(); else CP_WAIT0();
        __syncthreads();

        const float* Ab = As + ((kt - 1) & 1) * BM * 16;
        const float* Bb = Bs + ((kt - 1) & 1) * BN * 16;
#pragma unroll
        for (int ks = 0; ks < 2; ks++) {
            int kb = ks * 8;
            uint32_t af[MT][4], bf[NT][2];
#pragma unroll
            for (int mt = 0; mt < MT; mt++) {
                int r0 = wm + mt * 16 + gid;
                int r1 = r0 + 8;
                int c0 = kb + ctib, c1 = kb + ctib + 4;
                af[mt][0] = __float_as_uint(Ab[r0 * 16 + (((c0 >> 2) ^ (r0 & 3)) << 2) + ctib]);
                af[mt][1] = __float_as_uint(Ab[r1 * 16 + (((c0 >> 2) ^ (r1 & 3)) << 2) + ctib]);
                af[mt][2] = __float_as_uint(Ab[r0 * 16 + (((c1 >> 2) ^ (r0 & 3)) << 2) + ctib]);
                af[mt][3] = __float_as_uint(Ab[r1 * 16 + (((c1 >> 2) ^ (r1 & 3)) << 2) + ctib]);
            }
#pragma unroll
            for (int nt = 0; nt < NT; nt++) {
                int r = wn + nt * 8 + gid;
                int c0 = kb + ctib, c1 = kb + ctib + 4;
                bf[nt][0] = __float_as_uint(Bb[r * 16 + (((c0 >> 2) ^ (r & 3)) << 2) + ctib]);
                bf[nt][1] = __float_as_uint(Bb[r * 16 + (((c1 >> 2) ^ (r & 3)) << 2) + ctib]);
            }
#pragma unroll
            for (int mt = 0; mt < MT; mt++)
#pragma unroll
                for (int nt = 0; nt < NT; nt++) {
                    asm volatile(
                        "mma.sync.aligned.m16n8k8.row.col.f32.tf32.tf32.f32 "
                        "{%0,%1,%2,%3}, {%4,%5,%6,%7}, {%8,%9}, {%0,%1,%2,%3};"
                        : "+f"(acc[mt][nt][0]), "+f"(acc[mt][nt][1]),
                          "+f"(acc[mt][nt][2]), "+f"(acc[mt][nt][3])
                        : "r"(af[mt][0]), "r"(af[mt][1]),
                          "r"(af[mt][2]), "r"(af[mt][3]),
                          "r"(bf[nt][0]), "r"(bf[nt][1]));
                }
        }
        __syncthreads();
    }

    // ---- epilogue (float2 stores) ----
#pragma unroll
    for (int mt = 0; mt < MT; mt++) {
#pragma unroll
        for (int nt = 0; nt < NT; nt++) {
#pragma unroll
            for (int half = 0; half < 2; half++) {
                int gm = m0 + wm + mt * 16 + gid + half * 8;
                int gn = n0 + wn + nt * 8 + 2 * ctib;
                if (gn < N) {
                    float v0 = acc[mt][nt][half * 2];
                    float v1 = acc[mt][nt][half * 2 + 1];
                    if (EPI == 2) {
                        v0 += extra[gn];
                        v1 += extra[gn + 1];
                        v0 = (v0 > 20.f) ? v0 : log1pf(expf(v0));
                        v1 = (v1 > 20.f) ? v1 : log1pf(expf(v1));
                    }
                    *(float2*)&C[(size_t)gm * ldc + gn] = make_float2(v0, v1);
                }
            }
        }
    }
}

// ---------------- split-K reduce kernels ---------------------------------
__global__ void reduce_xp_kernel(const float4* __restrict__ part,
                                 float4* __restrict__ dst) {
    int i = blockIdx.x * blockDim.x + threadIdx.x;
    float4 s = part[i];
#pragma unroll
    for (int z = 1; z < 12; z++) {
        float4 v = part[i + z * (LSEQ * NXD / 4)];
        s.x += v.x; s.y += v.y; s.z += v.z; s.w += v.w;
    }
    dst[i] = s;
}
__global__ void reduce_out_kernel(const float4* __restrict__ part,
                                  const float4* __restrict__ res,
                                  float4* __restrict__ dst) {
    int i = blockIdx.x * blockDim.x + threadIdx.x;
    float4 s = res[i];
#pragma unroll
    for (int z = 0; z < 6; z++) {
        float4 v = part[i + z * (LSEQ * DMOD / 4)];
        s.x += v.x; s.y += v.y; s.z += v.z; s.w += v.w;
    }
    dst[i] = s;
}

// ---------------- layernorm: one block per row (768 cols) ----------------
__global__ void layernorm_kernel(const float* __restrict__ x,
                                 const float* __restrict__ w,
                                 const float* __restrict__ b,
                                 float* __restrict__ h) {
    int l = blockIdx.x;
    int t = threadIdx.x;
    const float* row = x + l * DMOD;
    float v[3];
    float sum = 0.f;
#pragma unroll
    for (int i = 0; i < 3; i++) { v[i] = row[t + 256 * i]; sum += v[i]; }

    __shared__ float red[256];
    red[t] = sum; __syncthreads();
    for (int s = 128; s > 0; s >>= 1) { if (t < s) red[t] += red[t + s]; __syncthreads(); }
    float mu = red[0] * (1.f / DMOD);
    __syncthreads();

    float sq = 0.f;
#pragma unroll
    for (int i = 0; i < 3; i++) { float d = v[i] - mu; sq += d * d; }
    red[t] = sq; __syncthreads();
    for (int s = 128; s > 0; s >>= 1) { if (t < s) red[t] += red[t + s]; __syncthreads(); }
    float rstd = rsqrtf(red[0] * (1.f / DMOD) + 1e-5f);

#pragma unroll
    for (int i = 0; i < 3; i++) {
        int c = t + 256 * i;
        h[l * DMOD + c] = (v[i] - mu) * rstd * w[c] + b[c];
    }
}

// ------------- causal depthwise conv (DC=4) + SiLU, float4 ---------------
__global__ void conv_silu_kernel(const float* __restrict__ xz,
                                 const float* __restrict__ cw,
                                 const float* __restrict__ cb,
                                 float* __restrict__ xc) {
    int idx = blockIdx.x * blockDim.x + threadIdx.x;   // LSEQ*DIN/4 threads
    if (idx >= LSEQ * (DIN / 4)) return;
    int l = idx / (DIN / 4);
    int d = (idx - l * (DIN / 4)) * 4;

    float4 acc = *(const float4*)&cb[d];
    float4 w0 = *(const float4*)&cw[(d + 0) * DCV];
    float4 w1 = *(const float4*)&cw[(d + 1) * DCV];
    float4 w2 = *(const float4*)&cw[(d + 2) * DCV];
    float4 w3 = *(const float4*)&cw[(d + 3) * DCV];
    const float* wj[4] = {&w0.x, &w1.x, &w2.x, &w3.x};

#pragma unroll
    for (int j = 0; j < DCV; j++) {
        int tl = l - (DCV - 1) + j;
        if (tl >= 0) {
            float4 v = *(const float4*)&xz[(size_t)tl * (2 * DIN) + d];
            acc.x += v.x * wj[0][j];
            acc.y += v.y * wj[1][j];
            acc.z += v.z * wj[2][j];
            acc.w += v.w * wj[3][j];
        }
    }
    float4 o;
    o.x = acc.x / (1.f + __expf(-acc.x));
    o.y = acc.y / (1.f + __expf(-acc.y));
    o.z = acc.z / (1.f + __expf(-acc.z));
    o.w = acc.w / (1.f + __expf(-acc.w));
    *(float4*)&xc[(size_t)l * DIN + d] = o;
}

// ---------------- selective scan: smem-staged, 1 warp/channel (R4) -------
__global__ __launch_bounds__(256) void scan_kernel(
        const float* __restrict__ xdbl, const float* __restrict__ dt,
        const float* __restrict__ xc, const float* __restrict__ A_log,
        float* __restrict__ y) {
    __shared__ float sBC[16][128];
    __shared__ float sdt[16][8];
    __shared__ float sxc[16][8];

    int tid  = threadIdx.x;
    int warp = tid >> 5;
    int lane = tid & 31;
    int d0 = blockIdx.x * 8;
    int d  = d0 + warp;

    float a0 = -__expf(A_log[d * DST + lane]);
    float a1 = -__expf(A_log[d * DST + 32 + lane]);
    float s0 = 0.f, s1 = 0.f;

    for (int lc = 0; lc < LSEQ; lc += 16) {
        __syncthreads();
#pragma unroll
        for (int k = 0; k < 2; k++) {
            int idx = tid + k * 256;
            int row = idx >> 5, c4 = (idx & 31) * 4;
            *(float4*)&sBC[row][c4] =
                *(const float4*)&xdbl[(size_t)(lc + row) * NXD + DRK + c4];
        }
        if (tid < 128) {
            int row = tid >> 3, dd = tid & 7;
            sdt[row][dd] = dt[(size_t)(lc + row) * DIN + d0 + dd];
        } else {
            int t2 = tid - 128;
            int row = t2 >> 3, dd = t2 & 7;
            sxc[row][dd] = xc[(size_t)(lc + row) * DIN + d0 + dd];
        }
        __syncthreads();

#pragma unroll 4
        for (int i = 0; i < 16; i++) {
            float dtv = sdt[i][warp];
            float u   = sxc[i][warp];
            float B0 = sBC[i][lane],      B1 = sBC[i][32 + lane];
            float C0 = sBC[i][64 + lane], C1 = sBC[i][96 + lane];
            float dbu = dtv * u;
            s0 = __expf(dtv * a0) * s0 + dbu * B0;
            s1 = __expf(dtv * a1) * s1 + dbu * B1;
            float p = s0 * C0 + s1 * C1;
#pragma unroll
            for (int off = 16; off > 0; off >>= 1)
                p += __shfl_xor_sync(0xffffffffu, p, off);
            if (lane == 0) y[(size_t)(lc + i) * DIN + d] = p;
        }
    }
}

// ------------- y2 = (y + xc*D) * silu(z), float4 --------------------------
__global__ void final_elem_kernel(const float* __restrict__ y,
                                  const float* __restrict__ xc,
                                  const float* __restrict__ xz,
                                  const float* __restrict__ Dv,
                                  float* __restrict__ y2) {
    int idx = blockIdx.x * blockDim.x + threadIdx.x;   // LSEQ*DIN/4 threads
    if (idx >= LSEQ * (DIN / 4)) return;
    int l = idx / (DIN / 4);
    int d = (idx - l * (DIN / 4)) * 4;

    float4 zv = *(const float4*)&xz[(size_t)l * (2 * DIN) + DIN + d];
    float4 yv = *(const float4*)&y[(size_t)l * DIN + d];
    float4 uv = *(const float4*)&xc[(size_t)l * DIN + d];
    float4 Dv4 = *(const float4*)&Dv[d];
    float4 o;
    o.x = (yv.x + uv.x * Dv4.x) * (zv.x / (1.f + __expf(-zv.x)));
    o.y = (yv.y + uv.y * Dv4.y) * (zv.y / (1.f + __expf(-zv.y)));
    o.z = (yv.z + uv.z * Dv4.z) * (zv.z / (1.f + __expf(-zv.z)));
    o.w = (yv.w + uv.w * Dv4.w) * (zv.w / (1.f + __expf(-zv.w)));
    *(float4*)&y2[(size_t)l * DIN + d] = o;
}

// ---------------- launch --------------------------------------------------
extern "C" void kernel_launch(void* const* d_in, const int* in_sizes, int n_in,
                              void* d_out, int out_size) {
    const float* x          = (const float*)d_in[0];
    const float* ln_w       = (const float*)d_in[1];
    const float* ln_b       = (const float*)d_in[2];
    const float* in_proj_w  = (const float*)d_in[3];
    const float* conv_w     = (const float*)d_in[4];
    const float* conv_b     = (const float*)d_in[5];
    const float* x_proj_w   = (const float*)d_in[6];
    const float* dt_proj_w  = (const float*)d_in[7];
    const float* dt_proj_b  = (const float*)d_in[8];
    const float* A_log      = (const float*)d_in[9];
    const float* Dvec       = (const float*)d_in[10];
    const float* out_proj_w = (const float*)d_in[11];
    float* out = (float*)d_out;

    float *h, *xz, *xc, *xdbl, *dt, *y, *y2, *xpp, *opp;
    cudaGetSymbolAddress((void**)&h,    g_h);
    cudaGetSymbolAddress((void**)&xz,   g_xz);
    cudaGetSymbolAddress((void**)&xc,   g_xconv);
    cudaGetSymbolAddress((void**)&xdbl, g_xdbl);
    cudaGetSymbolAddress((void**)&dt,   g_dt);
    cudaGetSymbolAddress((void**)&y,    g_y);
    cudaGetSymbolAddress((void**)&y2,   g_y2);
    cudaGetSymbolAddress((void**)&xpp,  g_xp_part);
    cudaGetSymbolAddress((void**)&opp,  g_op_part);

    // 1) layernorm
    layernorm_kernel<<<LSEQ, 256>>>(x, ln_w, ln_b, h);

    // 2) in_proj: [512,768] x [3072,768]^T -> [512,3072]   (96 CTAs, R4 config)
    mma_gemm<128, 128, 2, 4, 0><<<dim3(24, 4, 1), 256>>>(
        h, in_proj_w, xz, nullptr, LSEQ, 2 * DIN, DMOD, DMOD, 2 * DIN, DMOD);

    // 3) causal depthwise conv + silu -> xc [512,1536]  (float4)
    conv_silu_kernel<<<(LSEQ * DIN / 4) / 256, 256>>>(xz, conv_w, conv_b, xc);

    // 4) x_proj split-K(12): [512,1536] x [176,1536]^T -> partials (288 CTAs)
    mma_gemm<64, 64, 2, 2, 0><<<dim3(3, 8, 12), 128>>>(
        xc, x_proj_w, xpp, nullptr, LSEQ, NXD, DIN, DIN, NXD, 128);
    reduce_xp_kernel<<<(LSEQ * NXD / 4) / 256, 256>>>(
        (const float4*)xpp, (float4*)xdbl);

    // 5) dt_proj + softplus: [512,48](lda=176) x [1536,48]^T -> [512,1536] (192 CTAs)
    mma_gemm<64, 64, 2, 2, 2><<<dim3(24, 8, 1), 128>>>(
        xdbl, dt_proj_w, dt, dt_proj_b, LSEQ, DIN, NXD, DRK, DIN, DRK);

    // 6) selective scan -> y [512,1536]  (R4 form)
    scan_kernel<<<DIN / 8, 256>>>(xdbl, dt, xc, A_log, y);

    // 7) y2 = (y + xc*D) * silu(z)  (float4)
    final_elem_kernel<<<(LSEQ * DIN / 4) / 256, 256>>>(y, xc, xz, Dvec, y2);

    // 8) out_proj split-K(6): [512,1536] x [768,1536]^T -> partials (144 CTAs, R4 config)
    mma_gemm<128, 128, 2, 4, 0><<<dim3(6, 4, 6), 256>>>(
        y2, out_proj_w, opp, nullptr, LSEQ, DMOD, DIN, DIN, DMOD, 256);
    reduce_out_kernel<<<(LSEQ * DMOD / 4) / 256, 256>>>(
        (const float4*)opp, (const float4*)x, (float4*)out);
}